// round 15
// baseline (speedup 1.0000x reference)
#include <cuda_runtime.h>
#include <cuda_fp16.h>
#include <cstdint>
#include <math.h>

// ---------------------------------------------------------------------------
// Problem constants
// ---------------------------------------------------------------------------
#define B_     2
#define SQ_    2048
#define H_     4096
#define NH_    32
#define HD_    128
#define NG_    2
#define QKV_OUT_ (NH_*HD_ + 2*NG_*HD_)   // 4608
#define Q_SZ_    (NH_*HD_)               // 4096
#define KV_SZ_   (NG_*HD_)               // 256
#define REP_     (NH_/NG_)               // 16
#define MM_      (B_*SQ_)                // 4096
#define KSPLIT_  (2*H_)                  // 8192 (A-side hi|lo layout)

// ---------------------------------------------------------------------------
// Scratch
// ---------------------------------------------------------------------------
__device__ __half g_as[(size_t)MM_*KSPLIT_];        // A: [hi | lo] over 2K
__device__ __half g_bs[(size_t)QKV_OUT_*H_];        // B: hi only, [N, K]
__device__ __half g_qh[(size_t)B_*NH_*SQ_*HD_];
__device__ __half g_ql[(size_t)B_*NH_*SQ_*HD_];
__device__ __half g_kh[(size_t)B_*NG_*SQ_*HD_];
__device__ __half g_vh[(size_t)B_*NG_*SQ_*HD_];

// ---------------------------------------------------------------------------
// Helpers
// ---------------------------------------------------------------------------
__device__ __forceinline__ uint32_t smem_u32(const void* p) {
    uint32_t a;
    asm("{ .reg .u64 t; cvta.to.shared.u64 t, %1; cvt.u32.u64 %0, t; }" : "=r"(a) : "l"(p));
    return a;
}
__device__ __forceinline__ void cp_async16(uint32_t dst, const void* src) {
    asm volatile("cp.async.cg.shared.global [%0], [%1], 16;" :: "r"(dst), "l"(src));
}
__device__ __forceinline__ void cp_commit() {
    asm volatile("cp.async.commit_group;");
}
template<int N>
__device__ __forceinline__ void cp_wait() {
    asm volatile("cp.async.wait_group %0;" :: "n"(N));
}
__device__ __forceinline__ void ldm_x4(uint32_t& r0, uint32_t& r1, uint32_t& r2,
                                       uint32_t& r3, uint32_t addr) {
    asm volatile("ldmatrix.sync.aligned.m8n8.x4.shared.b16 {%0,%1,%2,%3}, [%4];"
                 : "=r"(r0), "=r"(r1), "=r"(r2), "=r"(r3) : "r"(addr));
}
__device__ __forceinline__ void ldm_x4_t(uint32_t& r0, uint32_t& r1, uint32_t& r2,
                                         uint32_t& r3, uint32_t addr) {
    asm volatile("ldmatrix.sync.aligned.m8n8.x4.trans.shared.b16 {%0,%1,%2,%3}, [%4];"
                 : "=r"(r0), "=r"(r1), "=r"(r2), "=r"(r3) : "r"(addr));
}
__device__ __forceinline__ void mma_f16(float* d, const uint32_t* a,
                                        uint32_t b0, uint32_t b1) {
    asm volatile(
        "mma.sync.aligned.m16n8k16.row.col.f32.f16.f16.f32 "
        "{%0,%1,%2,%3}, {%4,%5,%6,%7}, {%8,%9}, {%0,%1,%2,%3};"
        : "+f"(d[0]), "+f"(d[1]), "+f"(d[2]), "+f"(d[3])
        : "r"(a[0]), "r"(a[1]), "r"(a[2]), "r"(a[3]), "r"(b0), "r"(b1));
}
__device__ __forceinline__ uint32_t pack_h2(__half a, __half b) {
    return (uint32_t)__half_as_ushort(a) | ((uint32_t)__half_as_ushort(b) << 16);
}
__device__ __forceinline__ void split_pack(uint32_t& hi, uint32_t& lo, float p0, float p1) {
    __half h0 = __float2half(p0), h1 = __float2half(p1);
    __half e0 = __float2half(p0 - __half2float(h0));
    __half e1 = __float2half(p1 - __half2float(h1));
    hi = pack_h2(h0, h1);
    lo = pack_h2(e0, e1);
}

// ---------------------------------------------------------------------------
// fp32 -> fp16 split kernels
// ---------------------------------------------------------------------------
// A[M,K] fp32 -> As[M, 2K] fp16, segments [hi | lo]
__global__ __launch_bounds__(256)
void split_a_kernel(const float* __restrict__ A, __half* __restrict__ As,
                    int K, size_t n8)
{
    size_t g = (size_t)blockIdx.x * 256 + threadIdx.x;
    if (g >= n8) return;
    const int kpr = K / 8;
    const size_t m  = g / kpr;
    const int   k8  = (int)(g % kpr) * 8;
    float4 a0 = *(const float4*)&A[m * K + k8];
    float4 a1 = *(const float4*)&A[m * K + k8 + 4];
    float v[8] = {a0.x,a0.y,a0.z,a0.w,a1.x,a1.y,a1.z,a1.w};
    uint32_t hseg[4], lseg[4];
    #pragma unroll
    for (int j = 0; j < 4; j++) {
        __half h0 = __float2half(v[2*j]);
        __half h1 = __float2half(v[2*j+1]);
        hseg[j] = pack_h2(h0, h1);
        lseg[j] = pack_h2(__float2half(v[2*j]   - __half2float(h0)),
                          __float2half(v[2*j+1] - __half2float(h1)));
    }
    __half* row = As + m * (size_t)(2*K);
    *(uint4*)&row[k8]     = *(uint4*)hseg;
    *(uint4*)&row[K + k8] = *(uint4*)lseg;
}

// W[K,N] fp32 -> Bs[N, K] fp16 hi (transposed)
__global__ __launch_bounds__(256)
void transpose_h_kernel(const float* __restrict__ W, __half* __restrict__ Bs,
                        int K, int N)
{
    __shared__ float t[32][33];
    const int n0 = blockIdx.x * 32, k0 = blockIdx.y * 32;
    const int tx = threadIdx.x & 31, ty = threadIdx.x >> 5;
    #pragma unroll
    for (int i = 0; i < 4; i++)
        t[ty + 8*i][tx] = W[(size_t)(k0 + ty + 8*i) * N + n0 + tx];
    __syncthreads();
    #pragma unroll
    for (int i = 0; i < 4; i++) {
        float v = t[tx][ty + 8*i];
        Bs[(size_t)(n0 + ty + 8*i) * K + k0 + tx] = __float2half(v);
    }
}

// ---------------------------------------------------------------------------
// Dual-A fp16 GEMM, persistent-tile: C[M,N] = (Ah + Al)[M,K] @ Bh[N,K]^T.
// BM=BN=128, BK=32, 8 warps, 3-stage cp.async. Grid = 2 x #SM CTAs; each
// loops tiles with stride (row-major pid: concurrent CTAs share A rows).
// MODE 0: fp32 C. MODE 1: fused bias+RoPE+split+scatter (QKV).
// ---------------------------------------------------------------------------
#define GBM 128
#define GBN 128
#define GBK 32
#define GLD 40
#define TILE_BYTES  (GBM*GLD*2)              // 10240 per tile
#define STG_BYTES   (3*TILE_BYTES)           // Ah, Al, B = 30720
#define GSTAGES 3
#define GEMM_SMEM_BYTES (GSTAGES*STG_BYTES)  // 92160

template<int MODE>
__global__ __launch_bounds__(256)
void mma_gemm_kernel(const __half* __restrict__ Ag,
                     const __half* __restrict__ Bg,
                     const float* __restrict__ bias,
                     const float* __restrict__ cache,
                     float* __restrict__ C,
                     __half* __restrict__ qh, __half* __restrict__ ql,
                     __half* __restrict__ kh,
                     __half* __restrict__ vh,
                     int N, int K, int ntiles, int npn)
{
    extern __shared__ char dsm[];
    const uint32_t sbase = smem_u32(dsm);

    const int tid  = threadIdx.x;
    const int lane = tid & 31;
    const int wid  = tid >> 5;
    const int wm   = wid >> 2;
    const int wn   = wid & 3;

    const int NIT = K / GBK;    // 128

    const int a_r = lane & 15;
    const int a_c = (lane >> 4) << 3;
    const int b_r = (lane & 7) + ((lane >> 4) << 3);
    const int b_c = ((lane >> 3) & 1) << 3;
    const int cr = lane >> 2;
    const int cc = (lane & 3) * 2;

    for (int pid = blockIdx.x; pid < ntiles; pid += gridDim.x) {
        const int pm = pid / npn;
        const int pn = pid % npn;
        const int m0 = pm * GBM;
        const int n0 = pn * GBN;

        const __half* Ahr = Ag + (size_t)m0 * (2*K);
        const __half* Alr = Ahr + K;
        const __half* Brow = Bg + (size_t)n0 * K;

        auto issue_stage = [&](int kt, int slot) {
            const uint32_t st = sbase + slot * STG_BYTES;
            const int kO = kt * GBK;
            #pragma unroll
            for (int h = 0; h < 2; h++) {
                const int g = tid + h * 256;
                const int r = g >> 2, c = g & 3;
                const uint32_t doff = (r * GLD + c * 8) * 2;
                cp_async16(st + doff,                 Ahr + (size_t)r * (2*K) + kO + c * 8);
                cp_async16(st + TILE_BYTES + doff,    Alr + (size_t)r * (2*K) + kO + c * 8);
                cp_async16(st + 2*TILE_BYTES + doff,  Brow + (size_t)r * K + kO + c * 8);
            }
            cp_commit();
        };

        // guard: prior tile's smem reads must finish before refilling buffers
        __syncthreads();

        float acc[4][4][4];
        #pragma unroll
        for (int i = 0; i < 4; i++)
            #pragma unroll
            for (int j = 0; j < 4; j++)
                #pragma unroll
                for (int r = 0; r < 4; r++) acc[i][j][r] = 0.f;

        issue_stage(0, 0);
        issue_stage(1, 1);

        for (int kt = 0; kt < NIT; kt++) {
            cp_wait<1>();
            __syncthreads();
            if (kt + 2 < NIT) issue_stage(kt + 2, (kt + 2) % GSTAGES);
            else cp_commit();

            const uint32_t st = sbase + (kt % GSTAGES) * STG_BYTES;
            const uint32_t sah = st;
            const uint32_t sal = st + TILE_BYTES;
            const uint32_t sb  = st + 2*TILE_BYTES;

            #pragma unroll
            for (int ks = 0; ks < 2; ks++) {
                const int kb = ks * 16;
                uint32_t ah[4][4], al[4][4];
                #pragma unroll
                for (int i = 0; i < 4; i++) {
                    const uint32_t ro = ((wm*64 + i*16 + a_r) * GLD + kb + a_c) * 2;
                    ldm_x4(ah[i][0], ah[i][1], ah[i][2], ah[i][3], sah + ro);
                    ldm_x4(al[i][0], al[i][1], al[i][2], al[i][3], sal + ro);
                }
                uint32_t b[4][2];
                #pragma unroll
                for (int j = 0; j < 2; j++) {
                    uint32_t r0, r1, r2, r3;
                    ldm_x4(r0, r1, r2, r3,
                           sb + ((wn*32 + j*16 + b_r) * GLD + kb + b_c) * 2);
                    b[j*2][0]   = r0; b[j*2][1]   = r1;
                    b[j*2+1][0] = r2; b[j*2+1][1] = r3;
                }
                #pragma unroll
                for (int i = 0; i < 4; i++)
                    #pragma unroll
                    for (int j = 0; j < 4; j++) {
                        mma_f16(acc[i][j], ah[i], b[j][0], b[j][1]);
                        mma_f16(acc[i][j], al[i], b[j][0], b[j][1]);
                    }
            }
        }

        if (MODE == 0) {
            #pragma unroll
            for (int j = 0; j < 4; j++) {
                const int col = n0 + wn*32 + j*8 + cc;
                #pragma unroll
                for (int i = 0; i < 4; i++) {
                    const int row = m0 + wm*64 + i*16 + cr;
                    *(float2*)&C[(size_t)row * N + col] =
                        make_float2(acc[i][j][0], acc[i][j][1]);
                    *(float2*)&C[(size_t)(row + 8) * N + col] =
                        make_float2(acc[i][j][2], acc[i][j][3]);
                }
            }
        } else {
            const int hidx = n0 >> 7;            // 0..35
            #pragma unroll
            for (int j = 0; j < 4; j++) {
                const int d   = wn*32 + j*8 + cc;
                const float2 bv = *(const float2*)&bias[n0 + d];
                const bool rot = (d < 64);
                const int p = d >> 1;
                #pragma unroll
                for (int i = 0; i < 4; i++) {
                    #pragma unroll
                    for (int hrw = 0; hrw < 2; hrw++) {
                        const int row = m0 + wm*64 + i*16 + cr + hrw*8;
                        float x0 = acc[i][j][hrw*2+0] + bv.x;
                        float x1 = acc[i][j][hrw*2+1] + bv.y;
                        const int bb = row >> 11;
                        const int s  = row & (SQ_ - 1);
                        if (hidx < NH_ + NG_ && rot) {
                            const float2 c = *(const float2*)&cache[((size_t)s * 32 + p) * 2];
                            const float o0 = x0 * c.x - x1 * c.y;
                            const float o1 = x1 * c.x + x0 * c.y;
                            x0 = o0; x1 = o1;
                        }
                        if (hidx < NH_) {
                            uint32_t hi, lo;
                            split_pack(hi, lo, x0, x1);
                            const size_t off = (((size_t)bb * NH_ + hidx) * SQ_ + s) * HD_ + d;
                            *(uint32_t*)&qh[off] = hi;
                            *(uint32_t*)&ql[off] = lo;
                        } else if (hidx < NH_ + NG_) {
                            const size_t off = (((size_t)bb * NG_ + (hidx - NH_)) * SQ_ + s) * HD_ + d;
                            *(uint32_t*)&kh[off] = pack_h2(__float2half(x0), __float2half(x1));
                        } else {
                            const size_t off = (((size_t)bb * NG_ + (hidx - NH_ - NG_)) * SQ_ + s) * HD_ + d;
                            *(uint32_t*)&vh[off] = pack_h2(__float2half(x0), __float2half(x1));
                        }
                    }
                }
            }
        }
    }
}

// ---------------------------------------------------------------------------
// Tensor-core flash attention — FBM=64, 128 threads, 2 CTAs/SM.
// S-path: 2-term ((Qh+Ql)·Kh). PV-path: 2-term ((Ph+Pl)·Vh).
// ---------------------------------------------------------------------------
#define FBM 64
#define FBN 64
#define FNTHR 128
#define KV_TILE_B (FBN*256)          // 16 KB
#define FB_BUF    (2*KV_TILE_B)      // Kh, Vh = 32 KB
#define FLASH2_SMEM (2*FB_BUF)       // 64 KB

#define SWZ(row, gr) ((uint32_t)((row)*256 + ((((uint32_t)(gr)) ^ ((row)&7)) << 4)))

__global__ __launch_bounds__(FNTHR, 2)
void flash_mma_kernel(const __half* __restrict__ Qh, const __half* __restrict__ Ql,
                      const __half* __restrict__ Kh,
                      const __half* __restrict__ Vh,
                      __half* __restrict__ As)
{
    extern __shared__ char dsm[];
    const uint32_t sb = smem_u32(dsm);

    const int qb = gridDim.x - 1 - blockIdx.x;     // longest first
    const int h  = blockIdx.y;
    const int b  = blockIdx.z;
    const int g  = h / REP_;

    const int tid  = threadIdx.x;
    const int lane = tid & 31;
    const int wid  = tid >> 5;          // 0..3
    const int q0   = qb * FBM;
    const int qrow = q0 + wid * 16;
    const int r1   = lane >> 2;
    const int c2   = (lane & 3) * 2;
    const int grp  = lane >> 3;
    const int ri   = lane & 7;

    const float scale = 0.08838834764831845f;

    const __half* Qhp = Qh + ((size_t)b * NH_ + h) * SQ_ * HD_;
    const __half* Qlp = Ql + ((size_t)b * NH_ + h) * SQ_ * HD_;
    const __half* Khp = Kh + ((size_t)b * NG_ + g) * SQ_ * HD_;
    const __half* Vhp = Vh + ((size_t)b * NG_ + g) * SQ_ * HD_;

    uint32_t qfh[8][4], qfl[8][4];
    #pragma unroll
    for (int kc = 0; kc < 8; kc++) {
        const int col = kc * 16 + c2;
        qfh[kc][0] = *(const uint32_t*)&Qhp[(size_t)(qrow + r1)     * HD_ + col];
        qfh[kc][1] = *(const uint32_t*)&Qhp[(size_t)(qrow + r1 + 8) * HD_ + col];
        qfh[kc][2] = *(const uint32_t*)&Qhp[(size_t)(qrow + r1)     * HD_ + col + 8];
        qfh[kc][3] = *(const uint32_t*)&Qhp[(size_t)(qrow + r1 + 8) * HD_ + col + 8];
        qfl[kc][0] = *(const uint32_t*)&Qlp[(size_t)(qrow + r1)     * HD_ + col];
        qfl[kc][1] = *(const uint32_t*)&Qlp[(size_t)(qrow + r1 + 8) * HD_ + col];
        qfl[kc][2] = *(const uint32_t*)&Qlp[(size_t)(qrow + r1)     * HD_ + col + 8];
        qfl[kc][3] = *(const uint32_t*)&Qlp[(size_t)(qrow + r1 + 8) * HD_ + col + 8];
    }

    float o[16][4];
    #pragma unroll
    for (int j = 0; j < 16; j++)
        #pragma unroll
        for (int e = 0; e < 4; e++) o[j][e] = 0.f;
    float m1 = -1e30f, m2 = -1e30f, l1 = 0.f, l2 = 0.f;

    auto issue_kv = [&](int jt, int buf) {
        const uint32_t bbase = sb + (uint32_t)buf * FB_BUF;
        const int s0 = jt * FBN;
        const __half* srcs[2] = {
            Khp + (size_t)s0 * HD_, Vhp + (size_t)s0 * HD_ };
        #pragma unroll
        for (int t = 0; t < 2; t++) {
            #pragma unroll
            for (int i = 0; i < 8; i++) {
                const int gg = tid + i * FNTHR;     // 0..1023
                const int row = gg >> 4, c = gg & 15;
                cp_async16(bbase + t * KV_TILE_B + SWZ(row, c),
                           srcs[t] + (size_t)row * HD_ + c * 8);
            }
        }
        cp_commit();
    };

    const int njt = qb + 1;
    issue_kv(0, 0);

    for (int jt = 0; jt < njt; jt++) {
        if (jt + 1 < njt) { issue_kv(jt + 1, (jt + 1) & 1); cp_wait<1>(); }
        else              { cp_wait<0>(); }
        __syncthreads();

        const uint32_t bbase = sb + (uint32_t)(jt & 1) * FB_BUF;
        const uint32_t khb = bbase;
        const uint32_t vhb = bbase + KV_TILE_B;

        float s[8][4];
        #pragma unroll
        for (int j = 0; j < 8; j++)
            #pragma unroll
            for (int e = 0; e < 4; e++) s[j][e] = 0.f;

        #pragma unroll
        for (int kc = 0; kc < 8; kc++) {
            #pragma unroll
            for (int np = 0; np < 4; np++) {
                const int krow = np * 16 + ri + ((grp >> 1) << 3);
                const int kgr  = 2 * kc + (grp & 1);
                uint32_t h0,h1,h2,h3;
                ldm_x4(h0, h1, h2, h3, khb + SWZ(krow, kgr));
                mma_f16(s[2*np],   qfh[kc], h0, h1);
                mma_f16(s[2*np+1], qfh[kc], h2, h3);
                mma_f16(s[2*np],   qfl[kc], h0, h1);
                mma_f16(s[2*np+1], qfl[kc], h2, h3);
            }
        }

        #pragma unroll
        for (int j = 0; j < 8; j++)
            #pragma unroll
            for (int e = 0; e < 4; e++) s[j][e] *= scale;

        if (jt == qb) {
            const int row1 = qrow + r1, row2 = row1 + 8;
            #pragma unroll
            for (int j = 0; j < 8; j++) {
                const int col = jt * FBN + j * 8 + c2;
                if (col     > row1) s[j][0] = -1e30f;
                if (col + 1 > row1) s[j][1] = -1e30f;
                if (col     > row2) s[j][2] = -1e30f;
                if (col + 1 > row2) s[j][3] = -1e30f;
            }
        }

        float mx1 = -1e30f, mx2 = -1e30f;
        #pragma unroll
        for (int j = 0; j < 8; j++) {
            mx1 = fmaxf(mx1, fmaxf(s[j][0], s[j][1]));
            mx2 = fmaxf(mx2, fmaxf(s[j][2], s[j][3]));
        }
        mx1 = fmaxf(mx1, __shfl_xor_sync(0xffffffffu, mx1, 1));
        mx1 = fmaxf(mx1, __shfl_xor_sync(0xffffffffu, mx1, 2));
        mx2 = fmaxf(mx2, __shfl_xor_sync(0xffffffffu, mx2, 1));
        mx2 = fmaxf(mx2, __shfl_xor_sync(0xffffffffu, mx2, 2));

        const float mn1 = fmaxf(m1, mx1), mn2 = fmaxf(m2, mx2);
        const float a1 = __expf(m1 - mn1), a2 = __expf(m2 - mn2);
        m1 = mn1; m2 = mn2;

        float sum1 = 0.f, sum2 = 0.f;
        #pragma unroll
        for (int j = 0; j < 8; j++) {
            s[j][0] = __expf(s[j][0] - mn1);
            s[j][1] = __expf(s[j][1] - mn1);
            s[j][2] = __expf(s[j][2] - mn2);
            s[j][3] = __expf(s[j][3] - mn2);
            sum1 += s[j][0] + s[j][1];
            sum2 += s[j][2] + s[j][3];
        }
        sum1 += __shfl_xor_sync(0xffffffffu, sum1, 1);
        sum1 += __shfl_xor_sync(0xffffffffu, sum1, 2);
        sum2 += __shfl_xor_sync(0xffffffffu, sum2, 1);
        sum2 += __shfl_xor_sync(0xffffffffu, sum2, 2);
        l1 = l1 * a1 + sum1;
        l2 = l2 * a2 + sum2;

        #pragma unroll
        for (int j = 0; j < 16; j++) {
            o[j][0] *= a1; o[j][1] *= a1;
            o[j][2] *= a2; o[j][3] *= a2;
        }

        #pragma unroll
        for (int t = 0; t < 4; t++) {
            uint32_t ph[4], pl[4];
            split_pack(ph[0], pl[0], s[2*t][0],   s[2*t][1]);
            split_pack(ph[1], pl[1], s[2*t][2],   s[2*t][3]);
            split_pack(ph[2], pl[2], s[2*t+1][0], s[2*t+1][1]);
            split_pack(ph[3], pl[3], s[2*t+1][2], s[2*t+1][3]);
            #pragma unroll
            for (int np = 0; np < 8; np++) {
                const int vrow = t * 16 + ri + ((grp & 1) << 3);
                const int vgr  = 2 * np + (grp >> 1);
                uint32_t h0,h1,h2,h3;
                ldm_x4_t(h0, h1, h2, h3, vhb + SWZ(vrow, vgr));
                mma_f16(o[2*np],   ph, h0, h1);
                mma_f16(o[2*np+1], ph, h2, h3);
                mma_f16(o[2*np],   pl, h0, h1);
                mma_f16(o[2*np+1], pl, h2, h3);
            }
        }
        __syncthreads();
    }

    const float inv1 = 1.f / l1, inv2 = 1.f / l2;
    const size_t mr1 = (size_t)b * SQ_ + qrow + r1;
    const size_t mr2 = mr1 + 8;
    #pragma unroll
    for (int j = 0; j < 16; j++) {
        const int col = h * HD_ + j * 8 + c2;
        uint32_t hi, lo;
        split_pack(hi, lo, o[j][0] * inv1, o[j][1] * inv1);
        *(uint32_t*)&As[mr1 * KSPLIT_ + col]      = hi;
        *(uint32_t*)&As[mr1 * KSPLIT_ + H_ + col] = lo;
        split_pack(hi, lo, o[j][2] * inv2, o[j][3] * inv2);
        *(uint32_t*)&As[mr2 * KSPLIT_ + col]      = hi;
        *(uint32_t*)&As[mr2 * KSPLIT_ + H_ + col] = lo;
    }
}

// ---------------------------------------------------------------------------
// Launch
// ---------------------------------------------------------------------------
extern "C" void kernel_launch(void* const* d_in, const int* in_sizes, int n_in,
                              void* d_out, int out_size)
{
    const float* hidden = (const float*)d_in[0];
    const float* rope   = (const float*)d_in[1];
    const float* Wqkv   = (const float*)d_in[2];
    const float* bqkv   = (const float*)d_in[3];
    const float* Wd     = (const float*)d_in[4];
    float* out = (float*)d_out;

    __half *as, *bs, *qh, *ql, *kh, *vh;
    cudaGetSymbolAddress((void**)&as, g_as);
    cudaGetSymbolAddress((void**)&bs, g_bs);
    cudaGetSymbolAddress((void**)&qh, g_qh);
    cudaGetSymbolAddress((void**)&ql, g_ql);
    cudaGetSymbolAddress((void**)&kh, g_kh);
    cudaGetSymbolAddress((void**)&vh, g_vh);

    cudaFuncSetAttribute(mma_gemm_kernel<0>,
                         cudaFuncAttributeMaxDynamicSharedMemorySize, GEMM_SMEM_BYTES);
    cudaFuncSetAttribute(mma_gemm_kernel<1>,
                         cudaFuncAttributeMaxDynamicSharedMemorySize, GEMM_SMEM_BYTES);
    cudaFuncSetAttribute(flash_mma_kernel,
                         cudaFuncAttributeMaxDynamicSharedMemorySize, FLASH2_SMEM);

    int smCount = 148;
    cudaDeviceGetAttribute(&smCount, cudaDevAttrMultiProcessorCount, 0);
    const int gemm_ctas = 2 * smCount;

    const size_t n8 = (size_t)MM_ * H_ / 8;

    // 1) split hidden -> As [hi | lo]; transpose Wqkv hi -> Bs
    split_a_kernel<<<(unsigned)((n8 + 255) / 256), 256>>>(hidden, as, H_, n8);
    transpose_h_kernel<<<dim3(QKV_OUT_ / 32, H_ / 32), 256>>>(Wqkv, bs, H_, QKV_OUT_);

    // 2) QKV GEMM (persistent) with fused bias + RoPE + split + scatter
    {
        const int npn = QKV_OUT_ / GBN, ntiles = npn * (MM_ / GBM);
        mma_gemm_kernel<1><<<min(gemm_ctas, ntiles), 256, GEMM_SMEM_BYTES>>>(
            as, bs, bqkv, rope, nullptr, qh, ql, kh, vh, QKV_OUT_, H_, ntiles, npn);
    }

    // 3) tensor-core flash attention (2-term S, 2-term PV) -> split-As
    flash_mma_kernel<<<dim3(SQ_ / FBM, NH_, B_), FNTHR, FLASH2_SMEM>>>(
        qh, ql, kh, vh, as);

    // 4) transpose Wd hi -> Bs
    transpose_h_kernel<<<dim3(H_ / 32, H_ / 32), 256>>>(Wd, bs, H_, H_);

    // 5) out = ctx @ Wd (persistent)
    {
        const int npn = H_ / GBN, ntiles = npn * (MM_ / GBM);
        mma_gemm_kernel<0><<<min(gemm_ctas, ntiles), 256, GEMM_SMEM_BYTES>>>(
            as, bs, nullptr, nullptr, out, nullptr, nullptr, nullptr, nullptr,
            H_, H_, ntiles, npn);
    }
}

// round 16
// speedup vs baseline: 1.0246x; 1.0246x over previous
#include <cuda_runtime.h>
#include <cuda_fp16.h>
#include <cstdint>
#include <math.h>

// ---------------------------------------------------------------------------
// Problem constants
// ---------------------------------------------------------------------------
#define B_     2
#define SQ_    2048
#define H_     4096
#define NH_    32
#define HD_    128
#define NG_    2
#define QKV_OUT_ (NH_*HD_ + 2*NG_*HD_)   // 4608
#define Q_SZ_    (NH_*HD_)               // 4096
#define KV_SZ_   (NG_*HD_)               // 256
#define REP_     (NH_/NG_)               // 16
#define MM_      (B_*SQ_)                // 4096
#define KSPLIT_  (2*H_)                  // 8192 (A-side hi|lo layout)

// ---------------------------------------------------------------------------
// Scratch
// ---------------------------------------------------------------------------
__device__ __half g_as[(size_t)MM_*KSPLIT_];        // A: [hi | lo] over 2K
__device__ __half g_bs[(size_t)QKV_OUT_*H_];        // B: hi only, [N, K]
__device__ __half g_qh[(size_t)B_*NH_*SQ_*HD_];
__device__ __half g_ql[(size_t)B_*NH_*SQ_*HD_];
__device__ __half g_kh[(size_t)B_*NG_*SQ_*HD_];
__device__ __half g_vh[(size_t)B_*NG_*SQ_*HD_];

// ---------------------------------------------------------------------------
// Helpers
// ---------------------------------------------------------------------------
__device__ __forceinline__ uint32_t smem_u32(const void* p) {
    uint32_t a;
    asm("{ .reg .u64 t; cvta.to.shared.u64 t, %1; cvt.u32.u64 %0, t; }" : "=r"(a) : "l"(p));
    return a;
}
__device__ __forceinline__ void cp_async16(uint32_t dst, const void* src) {
    asm volatile("cp.async.cg.shared.global [%0], [%1], 16;" :: "r"(dst), "l"(src));
}
__device__ __forceinline__ void cp_commit() {
    asm volatile("cp.async.commit_group;");
}
template<int N>
__device__ __forceinline__ void cp_wait() {
    asm volatile("cp.async.wait_group %0;" :: "n"(N));
}
__device__ __forceinline__ void ldm_x4(uint32_t& r0, uint32_t& r1, uint32_t& r2,
                                       uint32_t& r3, uint32_t addr) {
    asm volatile("ldmatrix.sync.aligned.m8n8.x4.shared.b16 {%0,%1,%2,%3}, [%4];"
                 : "=r"(r0), "=r"(r1), "=r"(r2), "=r"(r3) : "r"(addr));
}
__device__ __forceinline__ void ldm_x4_t(uint32_t& r0, uint32_t& r1, uint32_t& r2,
                                         uint32_t& r3, uint32_t addr) {
    asm volatile("ldmatrix.sync.aligned.m8n8.x4.trans.shared.b16 {%0,%1,%2,%3}, [%4];"
                 : "=r"(r0), "=r"(r1), "=r"(r2), "=r"(r3) : "r"(addr));
}
__device__ __forceinline__ void mma_f16(float* d, const uint32_t* a,
                                        uint32_t b0, uint32_t b1) {
    asm volatile(
        "mma.sync.aligned.m16n8k16.row.col.f32.f16.f16.f32 "
        "{%0,%1,%2,%3}, {%4,%5,%6,%7}, {%8,%9}, {%0,%1,%2,%3};"
        : "+f"(d[0]), "+f"(d[1]), "+f"(d[2]), "+f"(d[3])
        : "r"(a[0]), "r"(a[1]), "r"(a[2]), "r"(a[3]), "r"(b0), "r"(b1));
}
__device__ __forceinline__ uint32_t pack_h2(__half a, __half b) {
    return (uint32_t)__half_as_ushort(a) | ((uint32_t)__half_as_ushort(b) << 16);
}
__device__ __forceinline__ void split_pack(uint32_t& hi, uint32_t& lo, float p0, float p1) {
    __half h0 = __float2half(p0), h1 = __float2half(p1);
    __half e0 = __float2half(p0 - __half2float(h0));
    __half e1 = __float2half(p1 - __half2float(h1));
    hi = pack_h2(h0, h1);
    lo = pack_h2(e0, e1);
}

// ---------------------------------------------------------------------------
// fp32 -> fp16 split kernels
// ---------------------------------------------------------------------------
// A[M,K] fp32 -> As[M, 2K] fp16, segments [hi | lo]
__global__ __launch_bounds__(256)
void split_a_kernel(const float* __restrict__ A, __half* __restrict__ As,
                    int K, size_t n8)
{
    size_t g = (size_t)blockIdx.x * 256 + threadIdx.x;
    if (g >= n8) return;
    const int kpr = K / 8;
    const size_t m  = g / kpr;
    const int   k8  = (int)(g % kpr) * 8;
    float4 a0 = *(const float4*)&A[m * K + k8];
    float4 a1 = *(const float4*)&A[m * K + k8 + 4];
    float v[8] = {a0.x,a0.y,a0.z,a0.w,a1.x,a1.y,a1.z,a1.w};
    uint32_t hseg[4], lseg[4];
    #pragma unroll
    for (int j = 0; j < 4; j++) {
        __half h0 = __float2half(v[2*j]);
        __half h1 = __float2half(v[2*j+1]);
        hseg[j] = pack_h2(h0, h1);
        lseg[j] = pack_h2(__float2half(v[2*j]   - __half2float(h0)),
                          __float2half(v[2*j+1] - __half2float(h1)));
    }
    __half* row = As + m * (size_t)(2*K);
    *(uint4*)&row[k8]     = *(uint4*)hseg;
    *(uint4*)&row[K + k8] = *(uint4*)lseg;
}

// W[K,N] fp32 -> Bs[N, K] fp16 hi (transposed)
__global__ __launch_bounds__(256)
void transpose_h_kernel(const float* __restrict__ W, __half* __restrict__ Bs,
                        int K, int N)
{
    __shared__ float t[32][33];
    const int n0 = blockIdx.x * 32, k0 = blockIdx.y * 32;
    const int tx = threadIdx.x & 31, ty = threadIdx.x >> 5;
    #pragma unroll
    for (int i = 0; i < 4; i++)
        t[ty + 8*i][tx] = W[(size_t)(k0 + ty + 8*i) * N + n0 + tx];
    __syncthreads();
    #pragma unroll
    for (int i = 0; i < 4; i++) {
        float v = t[tx][ty + 8*i];
        Bs[(size_t)(n0 + ty + 8*i) * K + k0 + tx] = __float2half(v);
    }
}

// ---------------------------------------------------------------------------
// Dual-A fp16 GEMM, persistent-tile, regs capped for 2 CTAs/SM:
// C[M,N] = (Ah + Al)[M,K] @ Bh[N,K]^T. BM=BN=128, BK=32, 8 warps, 3 stages.
// MODE 0: fp32 C. MODE 1: fused bias+RoPE+split+scatter (QKV).
// ---------------------------------------------------------------------------
#define GBM 128
#define GBN 128
#define GBK 32
#define GLD 40
#define TILE_BYTES  (GBM*GLD*2)              // 10240 per tile
#define STG_BYTES   (3*TILE_BYTES)           // Ah, Al, B = 30720
#define GSTAGES 3
#define GEMM_SMEM_BYTES (GSTAGES*STG_BYTES)  // 92160

template<int MODE>
__global__ __launch_bounds__(256, 2)
void mma_gemm_kernel(const __half* __restrict__ Ag,
                     const __half* __restrict__ Bg,
                     const float* __restrict__ bias,
                     const float* __restrict__ cache,
                     float* __restrict__ C,
                     __half* __restrict__ qh, __half* __restrict__ ql,
                     __half* __restrict__ kh,
                     __half* __restrict__ vh,
                     int N, int K, int ntiles, int npn)
{
    extern __shared__ char dsm[];
    const uint32_t sbase = smem_u32(dsm);

    const int tid  = threadIdx.x;
    const int lane = tid & 31;
    const int wid  = tid >> 5;
    const int wm   = wid >> 2;
    const int wn   = wid & 3;

    const int NIT = K / GBK;    // 128

    const int a_r = lane & 15;
    const int a_c = (lane >> 4) << 3;
    const int b_r = (lane & 7) + ((lane >> 4) << 3);
    const int b_c = ((lane >> 3) & 1) << 3;
    const int cr = lane >> 2;
    const int cc = (lane & 3) * 2;

    for (int pid = blockIdx.x; pid < ntiles; pid += gridDim.x) {
        const int pm = pid / npn;
        const int pn = pid - pm * npn;
        const int m0 = pm * GBM;
        const int n0 = pn * GBN;

        const __half* Ahr = Ag + (size_t)m0 * (2*K);
        const __half* Alr = Ahr + K;
        const __half* Brow = Bg + (size_t)n0 * K;

        auto issue_stage = [&](int kt, int slot) {
            const uint32_t st = sbase + slot * STG_BYTES;
            const int kO = kt * GBK;
            #pragma unroll
            for (int h = 0; h < 2; h++) {
                const int g = tid + h * 256;
                const int r = g >> 2, c = g & 3;
                const uint32_t doff = (r * GLD + c * 8) * 2;
                cp_async16(st + doff,                 Ahr + (size_t)r * (2*K) + kO + c * 8);
                cp_async16(st + TILE_BYTES + doff,    Alr + (size_t)r * (2*K) + kO + c * 8);
                cp_async16(st + 2*TILE_BYTES + doff,  Brow + (size_t)r * K + kO + c * 8);
            }
            cp_commit();
        };

        // guard: prior tile's smem reads must finish before refilling buffers
        __syncthreads();

        float acc[4][4][4];
        #pragma unroll
        for (int i = 0; i < 4; i++)
            #pragma unroll
            for (int j = 0; j < 4; j++)
                #pragma unroll
                for (int r = 0; r < 4; r++) acc[i][j][r] = 0.f;

        issue_stage(0, 0);
        issue_stage(1, 1);

        for (int kt = 0; kt < NIT; kt++) {
            cp_wait<1>();
            __syncthreads();
            if (kt + 2 < NIT) issue_stage(kt + 2, (kt + 2) % GSTAGES);
            else cp_commit();

            const uint32_t st = sbase + (kt % GSTAGES) * STG_BYTES;
            const uint32_t sah = st;
            const uint32_t sal = st + TILE_BYTES;
            const uint32_t sb  = st + 2*TILE_BYTES;

            #pragma unroll
            for (int ks = 0; ks < 2; ks++) {
                const int kb = ks * 16;
                uint32_t ah[4][4], al[4][4];
                #pragma unroll
                for (int i = 0; i < 4; i++) {
                    const uint32_t ro = ((wm*64 + i*16 + a_r) * GLD + kb + a_c) * 2;
                    ldm_x4(ah[i][0], ah[i][1], ah[i][2], ah[i][3], sah + ro);
                    ldm_x4(al[i][0], al[i][1], al[i][2], al[i][3], sal + ro);
                }
                uint32_t b[4][2];
                #pragma unroll
                for (int j = 0; j < 2; j++) {
                    uint32_t r0, r1, r2, r3;
                    ldm_x4(r0, r1, r2, r3,
                           sb + ((wn*32 + j*16 + b_r) * GLD + kb + b_c) * 2);
                    b[j*2][0]   = r0; b[j*2][1]   = r1;
                    b[j*2+1][0] = r2; b[j*2+1][1] = r3;
                }
                #pragma unroll
                for (int i = 0; i < 4; i++)
                    #pragma unroll
                    for (int j = 0; j < 4; j++) {
                        mma_f16(acc[i][j], ah[i], b[j][0], b[j][1]);
                        mma_f16(acc[i][j], al[i], b[j][0], b[j][1]);
                    }
            }
        }

        if (MODE == 0) {
            #pragma unroll
            for (int j = 0; j < 4; j++) {
                const int col = n0 + wn*32 + j*8 + cc;
                #pragma unroll
                for (int i = 0; i < 4; i++) {
                    const int row = m0 + wm*64 + i*16 + cr;
                    *(float2*)&C[(size_t)row * N + col] =
                        make_float2(acc[i][j][0], acc[i][j][1]);
                    *(float2*)&C[(size_t)(row + 8) * N + col] =
                        make_float2(acc[i][j][2], acc[i][j][3]);
                }
            }
        } else {
            const int hidx = n0 >> 7;            // 0..35
            #pragma unroll
            for (int j = 0; j < 4; j++) {
                const int d   = wn*32 + j*8 + cc;
                const float2 bv = *(const float2*)&bias[n0 + d];
                const bool rot = (d < 64);
                const int p = d >> 1;
                #pragma unroll
                for (int i = 0; i < 4; i++) {
                    #pragma unroll
                    for (int hrw = 0; hrw < 2; hrw++) {
                        const int row = m0 + wm*64 + i*16 + cr + hrw*8;
                        float x0 = acc[i][j][hrw*2+0] + bv.x;
                        float x1 = acc[i][j][hrw*2+1] + bv.y;
                        const int bb = row >> 11;
                        const int s  = row & (SQ_ - 1);
                        if (hidx < NH_ + NG_ && rot) {
                            const float2 c = *(const float2*)&cache[((size_t)s * 32 + p) * 2];
                            const float o0 = x0 * c.x - x1 * c.y;
                            const float o1 = x1 * c.x + x0 * c.y;
                            x0 = o0; x1 = o1;
                        }
                        if (hidx < NH_) {
                            uint32_t hi, lo;
                            split_pack(hi, lo, x0, x1);
                            const size_t off = (((size_t)bb * NH_ + hidx) * SQ_ + s) * HD_ + d;
                            *(uint32_t*)&qh[off] = hi;
                            *(uint32_t*)&ql[off] = lo;
                        } else if (hidx < NH_ + NG_) {
                            const size_t off = (((size_t)bb * NG_ + (hidx - NH_)) * SQ_ + s) * HD_ + d;
                            *(uint32_t*)&kh[off] = pack_h2(__float2half(x0), __float2half(x1));
                        } else {
                            const size_t off = (((size_t)bb * NG_ + (hidx - NH_ - NG_)) * SQ_ + s) * HD_ + d;
                            *(uint32_t*)&vh[off] = pack_h2(__float2half(x0), __float2half(x1));
                        }
                    }
                }
            }
        }
    }
}

// ---------------------------------------------------------------------------
// Tensor-core flash attention — FBM=64, 128 threads, 2 CTAs/SM.
// S-path: 2-term ((Qh+Ql)·Kh). PV-path: 2-term ((Ph+Pl)·Vh).
// ---------------------------------------------------------------------------
#define FBM 64
#define FBN 64
#define FNTHR 128
#define KV_TILE_B (FBN*256)          // 16 KB
#define FB_BUF    (2*KV_TILE_B)      // Kh, Vh = 32 KB
#define FLASH2_SMEM (2*FB_BUF)       // 64 KB

#define SWZ(row, gr) ((uint32_t)((row)*256 + ((((uint32_t)(gr)) ^ ((row)&7)) << 4)))

__global__ __launch_bounds__(FNTHR, 2)
void flash_mma_kernel(const __half* __restrict__ Qh, const __half* __restrict__ Ql,
                      const __half* __restrict__ Kh,
                      const __half* __restrict__ Vh,
                      __half* __restrict__ As)
{
    extern __shared__ char dsm[];
    const uint32_t sb = smem_u32(dsm);

    const int qb = gridDim.x - 1 - blockIdx.x;     // longest first
    const int h  = blockIdx.y;
    const int b  = blockIdx.z;
    const int g  = h / REP_;

    const int tid  = threadIdx.x;
    const int lane = tid & 31;
    const int wid  = tid >> 5;          // 0..3
    const int q0   = qb * FBM;
    const int qrow = q0 + wid * 16;
    const int r1   = lane >> 2;
    const int c2   = (lane & 3) * 2;
    const int grp  = lane >> 3;
    const int ri   = lane & 7;

    const float scale = 0.08838834764831845f;

    const __half* Qhp = Qh + ((size_t)b * NH_ + h) * SQ_ * HD_;
    const __half* Qlp = Ql + ((size_t)b * NH_ + h) * SQ_ * HD_;
    const __half* Khp = Kh + ((size_t)b * NG_ + g) * SQ_ * HD_;
    const __half* Vhp = Vh + ((size_t)b * NG_ + g) * SQ_ * HD_;

    uint32_t qfh[8][4], qfl[8][4];
    #pragma unroll
    for (int kc = 0; kc < 8; kc++) {
        const int col = kc * 16 + c2;
        qfh[kc][0] = *(const uint32_t*)&Qhp[(size_t)(qrow + r1)     * HD_ + col];
        qfh[kc][1] = *(const uint32_t*)&Qhp[(size_t)(qrow + r1 + 8) * HD_ + col];
        qfh[kc][2] = *(const uint32_t*)&Qhp[(size_t)(qrow + r1)     * HD_ + col + 8];
        qfh[kc][3] = *(const uint32_t*)&Qhp[(size_t)(qrow + r1 + 8) * HD_ + col + 8];
        qfl[kc][0] = *(const uint32_t*)&Qlp[(size_t)(qrow + r1)     * HD_ + col];
        qfl[kc][1] = *(const uint32_t*)&Qlp[(size_t)(qrow + r1 + 8) * HD_ + col];
        qfl[kc][2] = *(const uint32_t*)&Qlp[(size_t)(qrow + r1)     * HD_ + col + 8];
        qfl[kc][3] = *(const uint32_t*)&Qlp[(size_t)(qrow + r1 + 8) * HD_ + col + 8];
    }

    float o[16][4];
    #pragma unroll
    for (int j = 0; j < 16; j++)
        #pragma unroll
        for (int e = 0; e < 4; e++) o[j][e] = 0.f;
    float m1 = -1e30f, m2 = -1e30f, l1 = 0.f, l2 = 0.f;

    auto issue_kv = [&](int jt, int buf) {
        const uint32_t bbase = sb + (uint32_t)buf * FB_BUF;
        const int s0 = jt * FBN;
        const __half* srcs[2] = {
            Khp + (size_t)s0 * HD_, Vhp + (size_t)s0 * HD_ };
        #pragma unroll
        for (int t = 0; t < 2; t++) {
            #pragma unroll
            for (int i = 0; i < 8; i++) {
                const int gg = tid + i * FNTHR;     // 0..1023
                const int row = gg >> 4, c = gg & 15;
                cp_async16(bbase + t * KV_TILE_B + SWZ(row, c),
                           srcs[t] + (size_t)row * HD_ + c * 8);
            }
        }
        cp_commit();
    };

    const int njt = qb + 1;
    issue_kv(0, 0);

    for (int jt = 0; jt < njt; jt++) {
        if (jt + 1 < njt) { issue_kv(jt + 1, (jt + 1) & 1); cp_wait<1>(); }
        else              { cp_wait<0>(); }
        __syncthreads();

        const uint32_t bbase = sb + (uint32_t)(jt & 1) * FB_BUF;
        const uint32_t khb = bbase;
        const uint32_t vhb = bbase + KV_TILE_B;

        float s[8][4];
        #pragma unroll
        for (int j = 0; j < 8; j++)
            #pragma unroll
            for (int e = 0; e < 4; e++) s[j][e] = 0.f;

        #pragma unroll
        for (int kc = 0; kc < 8; kc++) {
            #pragma unroll
            for (int np = 0; np < 4; np++) {
                const int krow = np * 16 + ri + ((grp >> 1) << 3);
                const int kgr  = 2 * kc + (grp & 1);
                uint32_t h0,h1,h2,h3;
                ldm_x4(h0, h1, h2, h3, khb + SWZ(krow, kgr));
                mma_f16(s[2*np],   qfh[kc], h0, h1);
                mma_f16(s[2*np+1], qfh[kc], h2, h3);
                mma_f16(s[2*np],   qfl[kc], h0, h1);
                mma_f16(s[2*np+1], qfl[kc], h2, h3);
            }
        }

        #pragma unroll
        for (int j = 0; j < 8; j++)
            #pragma unroll
            for (int e = 0; e < 4; e++) s[j][e] *= scale;

        if (jt == qb) {
            const int row1 = qrow + r1, row2 = row1 + 8;
            #pragma unroll
            for (int j = 0; j < 8; j++) {
                const int col = jt * FBN + j * 8 + c2;
                if (col     > row1) s[j][0] = -1e30f;
                if (col + 1 > row1) s[j][1] = -1e30f;
                if (col     > row2) s[j][2] = -1e30f;
                if (col + 1 > row2) s[j][3] = -1e30f;
            }
        }

        float mx1 = -1e30f, mx2 = -1e30f;
        #pragma unroll
        for (int j = 0; j < 8; j++) {
            mx1 = fmaxf(mx1, fmaxf(s[j][0], s[j][1]));
            mx2 = fmaxf(mx2, fmaxf(s[j][2], s[j][3]));
        }
        mx1 = fmaxf(mx1, __shfl_xor_sync(0xffffffffu, mx1, 1));
        mx1 = fmaxf(mx1, __shfl_xor_sync(0xffffffffu, mx1, 2));
        mx2 = fmaxf(mx2, __shfl_xor_sync(0xffffffffu, mx2, 1));
        mx2 = fmaxf(mx2, __shfl_xor_sync(0xffffffffu, mx2, 2));

        const float mn1 = fmaxf(m1, mx1), mn2 = fmaxf(m2, mx2);
        const float a1 = __expf(m1 - mn1), a2 = __expf(m2 - mn2);
        m1 = mn1; m2 = mn2;

        float sum1 = 0.f, sum2 = 0.f;
        #pragma unroll
        for (int j = 0; j < 8; j++) {
            s[j][0] = __expf(s[j][0] - mn1);
            s[j][1] = __expf(s[j][1] - mn1);
            s[j][2] = __expf(s[j][2] - mn2);
            s[j][3] = __expf(s[j][3] - mn2);
            sum1 += s[j][0] + s[j][1];
            sum2 += s[j][2] + s[j][3];
        }
        sum1 += __shfl_xor_sync(0xffffffffu, sum1, 1);
        sum1 += __shfl_xor_sync(0xffffffffu, sum1, 2);
        sum2 += __shfl_xor_sync(0xffffffffu, sum2, 1);
        sum2 += __shfl_xor_sync(0xffffffffu, sum2, 2);
        l1 = l1 * a1 + sum1;
        l2 = l2 * a2 + sum2;

        #pragma unroll
        for (int j = 0; j < 16; j++) {
            o[j][0] *= a1; o[j][1] *= a1;
            o[j][2] *= a2; o[j][3] *= a2;
        }

        #pragma unroll
        for (int t = 0; t < 4; t++) {
            uint32_t ph[4], pl[4];
            split_pack(ph[0], pl[0], s[2*t][0],   s[2*t][1]);
            split_pack(ph[1], pl[1], s[2*t][2],   s[2*t][3]);
            split_pack(ph[2], pl[2], s[2*t+1][0], s[2*t+1][1]);
            split_pack(ph[3], pl[3], s[2*t+1][2], s[2*t+1][3]);
            #pragma unroll
            for (int np = 0; np < 8; np++) {
                const int vrow = t * 16 + ri + ((grp & 1) << 3);
                const int vgr  = 2 * np + (grp >> 1);
                uint32_t h0,h1,h2,h3;
                ldm_x4_t(h0, h1, h2, h3, vhb + SWZ(vrow, vgr));
                mma_f16(o[2*np],   ph, h0, h1);
                mma_f16(o[2*np+1], ph, h2, h3);
                mma_f16(o[2*np],   pl, h0, h1);
                mma_f16(o[2*np+1], pl, h2, h3);
            }
        }
        __syncthreads();
    }

    const float inv1 = 1.f / l1, inv2 = 1.f / l2;
    const size_t mr1 = (size_t)b * SQ_ + qrow + r1;
    const size_t mr2 = mr1 + 8;
    #pragma unroll
    for (int j = 0; j < 16; j++) {
        const int col = h * HD_ + j * 8 + c2;
        uint32_t hi, lo;
        split_pack(hi, lo, o[j][0] * inv1, o[j][1] * inv1);
        *(uint32_t*)&As[mr1 * KSPLIT_ + col]      = hi;
        *(uint32_t*)&As[mr1 * KSPLIT_ + H_ + col] = lo;
        split_pack(hi, lo, o[j][2] * inv2, o[j][3] * inv2);
        *(uint32_t*)&As[mr2 * KSPLIT_ + col]      = hi;
        *(uint32_t*)&As[mr2 * KSPLIT_ + H_ + col] = lo;
    }
}

// ---------------------------------------------------------------------------
// Launch
// ---------------------------------------------------------------------------
extern "C" void kernel_launch(void* const* d_in, const int* in_sizes, int n_in,
                              void* d_out, int out_size)
{
    const float* hidden = (const float*)d_in[0];
    const float* rope   = (const float*)d_in[1];
    const float* Wqkv   = (const float*)d_in[2];
    const float* bqkv   = (const float*)d_in[3];
    const float* Wd     = (const float*)d_in[4];
    float* out = (float*)d_out;

    __half *as, *bs, *qh, *ql, *kh, *vh;
    cudaGetSymbolAddress((void**)&as, g_as);
    cudaGetSymbolAddress((void**)&bs, g_bs);
    cudaGetSymbolAddress((void**)&qh, g_qh);
    cudaGetSymbolAddress((void**)&ql, g_ql);
    cudaGetSymbolAddress((void**)&kh, g_kh);
    cudaGetSymbolAddress((void**)&vh, g_vh);

    cudaFuncSetAttribute(mma_gemm_kernel<0>,
                         cudaFuncAttributeMaxDynamicSharedMemorySize, GEMM_SMEM_BYTES);
    cudaFuncSetAttribute(mma_gemm_kernel<1>,
                         cudaFuncAttributeMaxDynamicSharedMemorySize, GEMM_SMEM_BYTES);
    cudaFuncSetAttribute(flash_mma_kernel,
                         cudaFuncAttributeMaxDynamicSharedMemorySize, FLASH2_SMEM);

    int smCount = 148;
    cudaDeviceGetAttribute(&smCount, cudaDevAttrMultiProcessorCount, 0);
    const int gemm_ctas = 2 * smCount;

    const size_t n8 = (size_t)MM_ * H_ / 8;

    // 1) split hidden -> As [hi | lo]; transpose Wqkv hi -> Bs
    split_a_kernel<<<(unsigned)((n8 + 255) / 256), 256>>>(hidden, as, H_, n8);
    transpose_h_kernel<<<dim3(QKV_OUT_ / 32, H_ / 32), 256>>>(Wqkv, bs, H_, QKV_OUT_);

    // 2) QKV GEMM (persistent, 2 CTAs/SM) with fused bias + RoPE + split + scatter
    {
        const int npn = QKV_OUT_ / GBN, ntiles = npn * (MM_ / GBM);
        mma_gemm_kernel<1><<<min(gemm_ctas, ntiles), 256, GEMM_SMEM_BYTES>>>(
            as, bs, bqkv, rope, nullptr, qh, ql, kh, vh, QKV_OUT_, H_, ntiles, npn);
    }

    // 3) tensor-core flash attention (2-term S, 2-term PV) -> split-As
    flash_mma_kernel<<<dim3(SQ_ / FBM, NH_, B_), FNTHR, FLASH2_SMEM>>>(
        qh, ql, kh, vh, as);

    // 4) transpose Wd hi -> Bs
    transpose_h_kernel<<<dim3(H_ / 32, H_ / 32), 256>>>(Wd, bs, H_, H_);

    // 5) out = ctx @ Wd (persistent, 2 CTAs/SM)
    {
        const int npn = H_ / GBN, ntiles = npn * (MM_ / GBM);
        mma_gemm_kernel<0><<<min(gemm_ctas, ntiles), 256, GEMM_SMEM_BYTES>>>(
            as, bs, nullptr, nullptr, out, nullptr, nullptr, nullptr, nullptr,
            H_, H_, ntiles, npn);
    }
}

// round 17
// speedup vs baseline: 1.1589x; 1.1311x over previous
#include <cuda_runtime.h>
#include <cuda_fp16.h>
#include <cstdint>
#include <math.h>

// ---------------------------------------------------------------------------
// Problem constants
// ---------------------------------------------------------------------------
#define B_     2
#define SQ_    2048
#define H_     4096
#define NH_    32
#define HD_    128
#define NG_    2
#define QKV_OUT_ (NH_*HD_ + 2*NG_*HD_)   // 4608
#define Q_SZ_    (NH_*HD_)               // 4096
#define KV_SZ_   (NG_*HD_)               // 256
#define REP_     (NH_/NG_)               // 16
#define MM_      (B_*SQ_)                // 4096
#define KSPLIT_  (2*H_)                  // 8192 (A-side hi|lo layout)

// ---------------------------------------------------------------------------
// Scratch
// ---------------------------------------------------------------------------
__device__ __half g_as[(size_t)MM_*KSPLIT_];        // A: [hi | lo] over 2K
__device__ __half g_bs[(size_t)QKV_OUT_*H_];        // B: hi only, [N, K]
__device__ __half g_qh[(size_t)B_*NH_*SQ_*HD_];
__device__ __half g_ql[(size_t)B_*NH_*SQ_*HD_];
__device__ __half g_kh[(size_t)B_*NG_*SQ_*HD_];
__device__ __half g_vh[(size_t)B_*NG_*SQ_*HD_];

// ---------------------------------------------------------------------------
// Helpers
// ---------------------------------------------------------------------------
__device__ __forceinline__ uint32_t smem_u32(const void* p) {
    uint32_t a;
    asm("{ .reg .u64 t; cvta.to.shared.u64 t, %1; cvt.u32.u64 %0, t; }" : "=r"(a) : "l"(p));
    return a;
}
__device__ __forceinline__ void cp_async16(uint32_t dst, const void* src) {
    asm volatile("cp.async.cg.shared.global [%0], [%1], 16;" :: "r"(dst), "l"(src));
}
__device__ __forceinline__ void cp_commit() {
    asm volatile("cp.async.commit_group;");
}
template<int N>
__device__ __forceinline__ void cp_wait() {
    asm volatile("cp.async.wait_group %0;" :: "n"(N));
}
__device__ __forceinline__ void ldm_x4(uint32_t& r0, uint32_t& r1, uint32_t& r2,
                                       uint32_t& r3, uint32_t addr) {
    asm volatile("ldmatrix.sync.aligned.m8n8.x4.shared.b16 {%0,%1,%2,%3}, [%4];"
                 : "=r"(r0), "=r"(r1), "=r"(r2), "=r"(r3) : "r"(addr));
}
__device__ __forceinline__ void ldm_x4_t(uint32_t& r0, uint32_t& r1, uint32_t& r2,
                                         uint32_t& r3, uint32_t addr) {
    asm volatile("ldmatrix.sync.aligned.m8n8.x4.trans.shared.b16 {%0,%1,%2,%3}, [%4];"
                 : "=r"(r0), "=r"(r1), "=r"(r2), "=r"(r3) : "r"(addr));
}
__device__ __forceinline__ void mma_f16(float* d, const uint32_t* a,
                                        uint32_t b0, uint32_t b1) {
    asm volatile(
        "mma.sync.aligned.m16n8k16.row.col.f32.f16.f16.f32 "
        "{%0,%1,%2,%3}, {%4,%5,%6,%7}, {%8,%9}, {%0,%1,%2,%3};"
        : "+f"(d[0]), "+f"(d[1]), "+f"(d[2]), "+f"(d[3])
        : "r"(a[0]), "r"(a[1]), "r"(a[2]), "r"(a[3]), "r"(b0), "r"(b1));
}
__device__ __forceinline__ uint32_t pack_h2(__half a, __half b) {
    return (uint32_t)__half_as_ushort(a) | ((uint32_t)__half_as_ushort(b) << 16);
}
__device__ __forceinline__ void split_pack(uint32_t& hi, uint32_t& lo, float p0, float p1) {
    __half h0 = __float2half(p0), h1 = __float2half(p1);
    __half e0 = __float2half(p0 - __half2float(h0));
    __half e1 = __float2half(p1 - __half2float(h1));
    hi = pack_h2(h0, h1);
    lo = pack_h2(e0, e1);
}

// ---------------------------------------------------------------------------
// fp32 -> fp16 split kernels
// ---------------------------------------------------------------------------
// A[M,K] fp32 -> As[M, 2K] fp16, segments [hi | lo]
__global__ __launch_bounds__(256)
void split_a_kernel(const float* __restrict__ A, __half* __restrict__ As,
                    int K, size_t n8)
{
    size_t g = (size_t)blockIdx.x * 256 + threadIdx.x;
    if (g >= n8) return;
    const int kpr = K / 8;
    const size_t m  = g / kpr;
    const int   k8  = (int)(g % kpr) * 8;
    float4 a0 = *(const float4*)&A[m * K + k8];
    float4 a1 = *(const float4*)&A[m * K + k8 + 4];
    float v[8] = {a0.x,a0.y,a0.z,a0.w,a1.x,a1.y,a1.z,a1.w};
    uint32_t hseg[4], lseg[4];
    #pragma unroll
    for (int j = 0; j < 4; j++) {
        __half h0 = __float2half(v[2*j]);
        __half h1 = __float2half(v[2*j+1]);
        hseg[j] = pack_h2(h0, h1);
        lseg[j] = pack_h2(__float2half(v[2*j]   - __half2float(h0)),
                          __float2half(v[2*j+1] - __half2float(h1)));
    }
    __half* row = As + m * (size_t)(2*K);
    *(uint4*)&row[k8]     = *(uint4*)hseg;
    *(uint4*)&row[K + k8] = *(uint4*)lseg;
}

// W[K,N] fp32 -> Bs[N, K] fp16 hi (transposed)
__global__ __launch_bounds__(256)
void transpose_h_kernel(const float* __restrict__ W, __half* __restrict__ Bs,
                        int K, int N)
{
    __shared__ float t[32][33];
    const int n0 = blockIdx.x * 32, k0 = blockIdx.y * 32;
    const int tx = threadIdx.x & 31, ty = threadIdx.x >> 5;
    #pragma unroll
    for (int i = 0; i < 4; i++)
        t[ty + 8*i][tx] = W[(size_t)(k0 + ty + 8*i) * N + n0 + tx];
    __syncthreads();
    #pragma unroll
    for (int i = 0; i < 4; i++) {
        float v = t[tx][ty + 8*i];
        Bs[(size_t)(n0 + ty + 8*i) * K + k0 + tx] = __float2half(v);
    }
}

// ---------------------------------------------------------------------------
// Dual-A fp16 GEMM: C[M,N] = (Ah + Al)[M,K] @ Bh[N,K]^T.
// BM=BN=128, BK=32, 8 warps as 4x2 grid, warp tile m32 x n64 (better
// MMA:ldmatrix ratio than m64 x n32 at identical smem/occupancy).
// 3-stage cp.async. MODE 0: fp32 C. MODE 1: fused QKV epilogue.
// ---------------------------------------------------------------------------
#define GBM 128
#define GBN 128
#define GBK 32
#define GLD 40
#define TILE_BYTES  (GBM*GLD*2)              // 10240 per tile
#define STG_BYTES   (3*TILE_BYTES)           // Ah, Al, B = 30720
#define GSTAGES 3
#define GEMM_SMEM_BYTES (GSTAGES*STG_BYTES)  // 92160

template<int MODE>
__global__ __launch_bounds__(256)
void mma_gemm_kernel(const __half* __restrict__ Ag,
                     const __half* __restrict__ Bg,
                     const float* __restrict__ bias,
                     const float* __restrict__ cache,
                     float* __restrict__ C,
                     __half* __restrict__ qh, __half* __restrict__ ql,
                     __half* __restrict__ kh,
                     __half* __restrict__ vh,
                     int N, int K)
{
    extern __shared__ char dsm[];
    const uint32_t sbase = smem_u32(dsm);

    const int tid  = threadIdx.x;
    const int lane = tid & 31;
    const int wid  = tid >> 5;
    const int wm   = wid >> 1;          // 0..3 (m32 each)
    const int wn   = wid & 1;           // 0..1 (n64 each)
    const int m0   = blockIdx.y * GBM;
    const int n0   = blockIdx.x * GBN;

    const __half* Ahr = Ag + (size_t)m0 * (2*K);
    const __half* Alr = Ahr + K;
    const __half* Brow = Bg + (size_t)n0 * K;

    const int NIT = K / GBK;    // 128

    auto issue_stage = [&](int kt, int slot) {
        const uint32_t st = sbase + slot * STG_BYTES;
        const int kO = kt * GBK;
        #pragma unroll
        for (int h = 0; h < 2; h++) {
            const int g = tid + h * 256;
            const int r = g >> 2, c = g & 3;
            const uint32_t doff = (r * GLD + c * 8) * 2;
            cp_async16(st + doff,                 Ahr + (size_t)r * (2*K) + kO + c * 8);
            cp_async16(st + TILE_BYTES + doff,    Alr + (size_t)r * (2*K) + kO + c * 8);
            cp_async16(st + 2*TILE_BYTES + doff,  Brow + (size_t)r * K + kO + c * 8);
        }
        cp_commit();
    };

    float acc[2][8][4];
    #pragma unroll
    for (int i = 0; i < 2; i++)
        #pragma unroll
        for (int j = 0; j < 8; j++)
            #pragma unroll
            for (int r = 0; r < 4; r++) acc[i][j][r] = 0.f;

    issue_stage(0, 0);
    issue_stage(1, 1);

    const int a_r = lane & 15;
    const int a_c = (lane >> 4) << 3;
    const int b_r = (lane & 7) + ((lane >> 4) << 3);
    const int b_c = ((lane >> 3) & 1) << 3;

    for (int kt = 0; kt < NIT; kt++) {
        cp_wait<1>();
        __syncthreads();
        if (kt + 2 < NIT) issue_stage(kt + 2, (kt + 2) % GSTAGES);
        else cp_commit();

        const uint32_t st = sbase + (kt % GSTAGES) * STG_BYTES;
        const uint32_t sah = st;
        const uint32_t sal = st + TILE_BYTES;
        const uint32_t sb  = st + 2*TILE_BYTES;

        #pragma unroll
        for (int ks = 0; ks < 2; ks++) {
            const int kb = ks * 16;
            uint32_t ah[2][4], al[2][4];
            #pragma unroll
            for (int i = 0; i < 2; i++) {
                const uint32_t ro = ((wm*32 + i*16 + a_r) * GLD + kb + a_c) * 2;
                ldm_x4(ah[i][0], ah[i][1], ah[i][2], ah[i][3], sah + ro);
                ldm_x4(al[i][0], al[i][1], al[i][2], al[i][3], sal + ro);
            }
            uint32_t b[8][2];
            #pragma unroll
            for (int j = 0; j < 4; j++) {
                uint32_t r0, r1, r2, r3;
                ldm_x4(r0, r1, r2, r3,
                       sb + ((wn*64 + j*16 + b_r) * GLD + kb + b_c) * 2);
                b[j*2][0]   = r0; b[j*2][1]   = r1;
                b[j*2+1][0] = r2; b[j*2+1][1] = r3;
            }
            #pragma unroll
            for (int i = 0; i < 2; i++)
                #pragma unroll
                for (int j = 0; j < 8; j++) {
                    mma_f16(acc[i][j], ah[i], b[j][0], b[j][1]);
                    mma_f16(acc[i][j], al[i], b[j][0], b[j][1]);
                }
        }
    }

    const int cr = lane >> 2;
    const int cc = (lane & 3) * 2;

    if (MODE == 0) {
        #pragma unroll
        for (int j = 0; j < 8; j++) {
            const int col = n0 + wn*64 + j*8 + cc;
            #pragma unroll
            for (int i = 0; i < 2; i++) {
                const int row = m0 + wm*32 + i*16 + cr;
                *(float2*)&C[(size_t)row * N + col] =
                    make_float2(acc[i][j][0], acc[i][j][1]);
                *(float2*)&C[(size_t)(row + 8) * N + col] =
                    make_float2(acc[i][j][2], acc[i][j][3]);
            }
        }
    } else {
        const int hidx = n0 >> 7;            // 0..35 (one head per CTA col-block)
        #pragma unroll
        for (int j = 0; j < 8; j++) {
            const int d   = wn*64 + j*8 + cc;         // 0..126 (even), within head
            const float2 bv = *(const float2*)&bias[n0 + d];
            const bool rot = (d < 64);
            const int p = d >> 1;
            #pragma unroll
            for (int i = 0; i < 2; i++) {
                #pragma unroll
                for (int hrw = 0; hrw < 2; hrw++) {
                    const int row = m0 + wm*32 + i*16 + cr + hrw*8;
                    float x0 = acc[i][j][hrw*2+0] + bv.x;
                    float x1 = acc[i][j][hrw*2+1] + bv.y;
                    const int bb = row >> 11;
                    const int s  = row & (SQ_ - 1);
                    if (hidx < NH_ + NG_ && rot) {
                        const float2 c = *(const float2*)&cache[((size_t)s * 32 + p) * 2];
                        const float o0 = x0 * c.x - x1 * c.y;
                        const float o1 = x1 * c.x + x0 * c.y;
                        x0 = o0; x1 = o1;
                    }
                    if (hidx < NH_) {
                        uint32_t hi, lo;
                        split_pack(hi, lo, x0, x1);
                        const size_t off = (((size_t)bb * NH_ + hidx) * SQ_ + s) * HD_ + d;
                        *(uint32_t*)&qh[off] = hi;
                        *(uint32_t*)&ql[off] = lo;
                    } else if (hidx < NH_ + NG_) {
                        const size_t off = (((size_t)bb * NG_ + (hidx - NH_)) * SQ_ + s) * HD_ + d;
                        *(uint32_t*)&kh[off] = pack_h2(__float2half(x0), __float2half(x1));
                    } else {
                        const size_t off = (((size_t)bb * NG_ + (hidx - NH_ - NG_)) * SQ_ + s) * HD_ + d;
                        *(uint32_t*)&vh[off] = pack_h2(__float2half(x0), __float2half(x1));
                    }
                }
            }
        }
    }
}

// ---------------------------------------------------------------------------
// Tensor-core flash attention — FBM=64, 128 threads, 2 CTAs/SM (R14 exact).
// S-path: 2-term ((Qh+Ql)·Kh). PV-path: 2-term ((Ph+Pl)·Vh).
// ---------------------------------------------------------------------------
#define FBM 64
#define FBN 64
#define FNTHR 128
#define KV_TILE_B (FBN*256)          // 16 KB
#define FB_BUF    (2*KV_TILE_B)      // Kh, Vh = 32 KB
#define FLASH2_SMEM (2*FB_BUF)       // 64 KB

#define SWZ(row, gr) ((uint32_t)((row)*256 + ((((uint32_t)(gr)) ^ ((row)&7)) << 4)))

__global__ __launch_bounds__(FNTHR, 2)
void flash_mma_kernel(const __half* __restrict__ Qh, const __half* __restrict__ Ql,
                      const __half* __restrict__ Kh,
                      const __half* __restrict__ Vh,
                      __half* __restrict__ As)
{
    extern __shared__ char dsm[];
    const uint32_t sb = smem_u32(dsm);

    const int qb = gridDim.x - 1 - blockIdx.x;     // longest first
    const int h  = blockIdx.y;
    const int b  = blockIdx.z;
    const int g  = h / REP_;

    const int tid  = threadIdx.x;
    const int lane = tid & 31;
    const int wid  = tid >> 5;          // 0..3
    const int q0   = qb * FBM;
    const int qrow = q0 + wid * 16;
    const int r1   = lane >> 2;
    const int c2   = (lane & 3) * 2;
    const int grp  = lane >> 3;
    const int ri   = lane & 7;

    const float scale = 0.08838834764831845f;

    const __half* Qhp = Qh + ((size_t)b * NH_ + h) * SQ_ * HD_;
    const __half* Qlp = Ql + ((size_t)b * NH_ + h) * SQ_ * HD_;
    const __half* Khp = Kh + ((size_t)b * NG_ + g) * SQ_ * HD_;
    const __half* Vhp = Vh + ((size_t)b * NG_ + g) * SQ_ * HD_;

    uint32_t qfh[8][4], qfl[8][4];
    #pragma unroll
    for (int kc = 0; kc < 8; kc++) {
        const int col = kc * 16 + c2;
        qfh[kc][0] = *(const uint32_t*)&Qhp[(size_t)(qrow + r1)     * HD_ + col];
        qfh[kc][1] = *(const uint32_t*)&Qhp[(size_t)(qrow + r1 + 8) * HD_ + col];
        qfh[kc][2] = *(const uint32_t*)&Qhp[(size_t)(qrow + r1)     * HD_ + col + 8];
        qfh[kc][3] = *(const uint32_t*)&Qhp[(size_t)(qrow + r1 + 8) * HD_ + col + 8];
        qfl[kc][0] = *(const uint32_t*)&Qlp[(size_t)(qrow + r1)     * HD_ + col];
        qfl[kc][1] = *(const uint32_t*)&Qlp[(size_t)(qrow + r1 + 8) * HD_ + col];
        qfl[kc][2] = *(const uint32_t*)&Qlp[(size_t)(qrow + r1)     * HD_ + col + 8];
        qfl[kc][3] = *(const uint32_t*)&Qlp[(size_t)(qrow + r1 + 8) * HD_ + col + 8];
    }

    float o[16][4];
    #pragma unroll
    for (int j = 0; j < 16; j++)
        #pragma unroll
        for (int e = 0; e < 4; e++) o[j][e] = 0.f;
    float m1 = -1e30f, m2 = -1e30f, l1 = 0.f, l2 = 0.f;

    auto issue_kv = [&](int jt, int buf) {
        const uint32_t bbase = sb + (uint32_t)buf * FB_BUF;
        const int s0 = jt * FBN;
        const __half* srcs[2] = {
            Khp + (size_t)s0 * HD_, Vhp + (size_t)s0 * HD_ };
        #pragma unroll
        for (int t = 0; t < 2; t++) {
            #pragma unroll
            for (int i = 0; i < 8; i++) {
                const int gg = tid + i * FNTHR;     // 0..1023
                const int row = gg >> 4, c = gg & 15;
                cp_async16(bbase + t * KV_TILE_B + SWZ(row, c),
                           srcs[t] + (size_t)row * HD_ + c * 8);
            }
        }
        cp_commit();
    };

    const int njt = qb + 1;
    issue_kv(0, 0);

    for (int jt = 0; jt < njt; jt++) {
        if (jt + 1 < njt) { issue_kv(jt + 1, (jt + 1) & 1); cp_wait<1>(); }
        else              { cp_wait<0>(); }
        __syncthreads();

        const uint32_t bbase = sb + (uint32_t)(jt & 1) * FB_BUF;
        const uint32_t khb = bbase;
        const uint32_t vhb = bbase + KV_TILE_B;

        float s[8][4];
        #pragma unroll
        for (int j = 0; j < 8; j++)
            #pragma unroll
            for (int e = 0; e < 4; e++) s[j][e] = 0.f;

        #pragma unroll
        for (int kc = 0; kc < 8; kc++) {
            #pragma unroll
            for (int np = 0; np < 4; np++) {
                const int krow = np * 16 + ri + ((grp >> 1) << 3);
                const int kgr  = 2 * kc + (grp & 1);
                uint32_t h0,h1,h2,h3;
                ldm_x4(h0, h1, h2, h3, khb + SWZ(krow, kgr));
                mma_f16(s[2*np],   qfh[kc], h0, h1);
                mma_f16(s[2*np+1], qfh[kc], h2, h3);
                mma_f16(s[2*np],   qfl[kc], h0, h1);
                mma_f16(s[2*np+1], qfl[kc], h2, h3);
            }
        }

        #pragma unroll
        for (int j = 0; j < 8; j++)
            #pragma unroll
            for (int e = 0; e < 4; e++) s[j][e] *= scale;

        if (jt == qb) {
            const int row1 = qrow + r1, row2 = row1 + 8;
            #pragma unroll
            for (int j = 0; j < 8; j++) {
                const int col = jt * FBN + j * 8 + c2;
                if (col     > row1) s[j][0] = -1e30f;
                if (col + 1 > row1) s[j][1] = -1e30f;
                if (col     > row2) s[j][2] = -1e30f;
                if (col + 1 > row2) s[j][3] = -1e30f;
            }
        }

        float mx1 = -1e30f, mx2 = -1e30f;
        #pragma unroll
        for (int j = 0; j < 8; j++) {
            mx1 = fmaxf(mx1, fmaxf(s[j][0], s[j][1]));
            mx2 = fmaxf(mx2, fmaxf(s[j][2], s[j][3]));
        }
        mx1 = fmaxf(mx1, __shfl_xor_sync(0xffffffffu, mx1, 1));
        mx1 = fmaxf(mx1, __shfl_xor_sync(0xffffffffu, mx1, 2));
        mx2 = fmaxf(mx2, __shfl_xor_sync(0xffffffffu, mx2, 1));
        mx2 = fmaxf(mx2, __shfl_xor_sync(0xffffffffu, mx2, 2));

        const float mn1 = fmaxf(m1, mx1), mn2 = fmaxf(m2, mx2);
        const float a1 = __expf(m1 - mn1), a2 = __expf(m2 - mn2);
        m1 = mn1; m2 = mn2;

        float sum1 = 0.f, sum2 = 0.f;
        #pragma unroll
        for (int j = 0; j < 8; j++) {
            s[j][0] = __expf(s[j][0] - mn1);
            s[j][1] = __expf(s[j][1] - mn1);
            s[j][2] = __expf(s[j][2] - mn2);
            s[j][3] = __expf(s[j][3] - mn2);
            sum1 += s[j][0] + s[j][1];
            sum2 += s[j][2] + s[j][3];
        }
        sum1 += __shfl_xor_sync(0xffffffffu, sum1, 1);
        sum1 += __shfl_xor_sync(0xffffffffu, sum1, 2);
        sum2 += __shfl_xor_sync(0xffffffffu, sum2, 1);
        sum2 += __shfl_xor_sync(0xffffffffu, sum2, 2);
        l1 = l1 * a1 + sum1;
        l2 = l2 * a2 + sum2;

        #pragma unroll
        for (int j = 0; j < 16; j++) {
            o[j][0] *= a1; o[j][1] *= a1;
            o[j][2] *= a2; o[j][3] *= a2;
        }

        #pragma unroll
        for (int t = 0; t < 4; t++) {
            uint32_t ph[4], pl[4];
            split_pack(ph[0], pl[0], s[2*t][0],   s[2*t][1]);
            split_pack(ph[1], pl[1], s[2*t][2],   s[2*t][3]);
            split_pack(ph[2], pl[2], s[2*t+1][0], s[2*t+1][1]);
            split_pack(ph[3], pl[3], s[2*t+1][2], s[2*t+1][3]);
            #pragma unroll
            for (int np = 0; np < 8; np++) {
                const int vrow = t * 16 + ri + ((grp & 1) << 3);
                const int vgr  = 2 * np + (grp >> 1);
                uint32_t h0,h1,h2,h3;
                ldm_x4_t(h0, h1, h2, h3, vhb + SWZ(vrow, vgr));
                mma_f16(o[2*np],   ph, h0, h1);
                mma_f16(o[2*np+1], ph, h2, h3);
                mma_f16(o[2*np],   pl, h0, h1);
                mma_f16(o[2*np+1], pl, h2, h3);
            }
        }
        __syncthreads();
    }

    const float inv1 = 1.f / l1, inv2 = 1.f / l2;
    const size_t mr1 = (size_t)b * SQ_ + qrow + r1;
    const size_t mr2 = mr1 + 8;
    #pragma unroll
    for (int j = 0; j < 16; j++) {
        const int col = h * HD_ + j * 8 + c2;
        uint32_t hi, lo;
        split_pack(hi, lo, o[j][0] * inv1, o[j][1] * inv1);
        *(uint32_t*)&As[mr1 * KSPLIT_ + col]      = hi;
        *(uint32_t*)&As[mr1 * KSPLIT_ + H_ + col] = lo;
        split_pack(hi, lo, o[j][2] * inv2, o[j][3] * inv2);
        *(uint32_t*)&As[mr2 * KSPLIT_ + col]      = hi;
        *(uint32_t*)&As[mr2 * KSPLIT_ + H_ + col] = lo;
    }
}

// ---------------------------------------------------------------------------
// Launch
// ---------------------------------------------------------------------------
extern "C" void kernel_launch(void* const* d_in, const int* in_sizes, int n_in,
                              void* d_out, int out_size)
{
    const float* hidden = (const float*)d_in[0];
    const float* rope   = (const float*)d_in[1];
    const float* Wqkv   = (const float*)d_in[2];
    const float* bqkv   = (const float*)d_in[3];
    const float* Wd     = (const float*)d_in[4];
    float* out = (float*)d_out;

    __half *as, *bs, *qh, *ql, *kh, *vh;
    cudaGetSymbolAddress((void**)&as, g_as);
    cudaGetSymbolAddress((void**)&bs, g_bs);
    cudaGetSymbolAddress((void**)&qh, g_qh);
    cudaGetSymbolAddress((void**)&ql, g_ql);
    cudaGetSymbolAddress((void**)&kh, g_kh);
    cudaGetSymbolAddress((void**)&vh, g_vh);

    cudaFuncSetAttribute(mma_gemm_kernel<0>,
                         cudaFuncAttributeMaxDynamicSharedMemorySize, GEMM_SMEM_BYTES);
    cudaFuncSetAttribute(mma_gemm_kernel<1>,
                         cudaFuncAttributeMaxDynamicSharedMemorySize, GEMM_SMEM_BYTES);
    cudaFuncSetAttribute(flash_mma_kernel,
                         cudaFuncAttributeMaxDynamicSharedMemorySize, FLASH2_SMEM);

    const size_t n8 = (size_t)MM_ * H_ / 8;

    // 1) split hidden -> As [hi | lo]; transpose Wqkv hi -> Bs
    split_a_kernel<<<(unsigned)((n8 + 255) / 256), 256>>>(hidden, as, H_, n8);
    transpose_h_kernel<<<dim3(QKV_OUT_ / 32, H_ / 32), 256>>>(Wqkv, bs, H_, QKV_OUT_);

    // 2) QKV GEMM (dual-A, m32xn64 warp tile) + fused bias/RoPE/split/scatter
    mma_gemm_kernel<1><<<dim3(QKV_OUT_ / GBN, MM_ / GBM), 256, GEMM_SMEM_BYTES>>>(
        as, bs, bqkv, rope, nullptr, qh, ql, kh, vh, QKV_OUT_, H_);

    // 3) tensor-core flash attention (2-term S, 2-term PV) -> split-As
    flash_mma_kernel<<<dim3(SQ_ / FBM, NH_, B_), FNTHR, FLASH2_SMEM>>>(
        qh, ql, kh, vh, as);

    // 4) transpose Wd hi -> Bs
    transpose_h_kernel<<<dim3(H_ / 32, H_ / 32), 256>>>(Wd, bs, H_, H_);

    // 5) out = ctx @ Wd (dual-A, m32xn64 warp tile)
    mma_gemm_kernel<0><<<dim3(H_ / GBN, MM_ / GBM), 256, GEMM_SMEM_BYTES>>>(
        as, bs, nullptr, nullptr, out, nullptr, nullptr, nullptr, nullptr,
        H_, H_);
}